// round 8
// baseline (speedup 1.0000x reference)
#include <cuda_runtime.h>

#define DFEAT   64
#define DH2     (DFEAT / 2)          // 32 float2 per row
#define MAX_NODES 50000
#define MAX_EDGES 800000
#define NBLK    148                  // <= SM count; all CTAs resident (1/SM)
#define NTHR    1024
#define SCAN_T  1024
#define MAX_TILES ((MAX_NODES + SCAN_T - 1) / SCAN_T)

// ---- scratch (device globals; no allocation allowed) ----
__device__ int    g_deg[MAX_NODES];
__device__ int    g_cnt[MAX_NODES];
__device__ float  g_dinv[MAX_NODES];
__device__ int    g_rowptr[MAX_NODES + 1];
__device__ int    g_cursor[MAX_NODES];
__device__ int    g_bsum[MAX_TILES];
__device__ int2   g_edge[MAX_EDGES];            // {col, float_as_int(w)}
__device__ float2 g_x1[MAX_NODES * DH2];
__device__ float2 g_x2[MAX_NODES * DH2];
__device__ unsigned g_barcnt = 0;
__device__ unsigned g_bargen = 0;

// Software grid barrier. Safe: grid = NBLK <= SMs and __launch_bounds__(1024,1)
// guarantees every CTA is resident. Generation counter only grows (compared by
// equality, so persistence across graph replays is harmless); count self-resets.
__device__ __forceinline__ void gbar() {
    __syncthreads();
    if (threadIdx.x == 0) {
        __threadfence();
        unsigned my = *((volatile unsigned*)&g_bargen);
        if (atomicAdd(&g_barcnt, 1u) == gridDim.x - 1) {
            g_barcnt = 0;
            __threadfence();
            atomicAdd(&g_bargen, 1u);
        } else {
            while (*((volatile unsigned*)&g_bargen) == my) { __nanosleep(64); }
        }
    }
    __syncthreads();
}

// One warp per row (grid-strided). Lane owns one float2 (features 2l, 2l+1).
// Per edge: one LDG.64 for {col,w} + one LDG.64 gather (256B/warp, coalesced).
__device__ __forceinline__ void spmm_pass(const float2* __restrict__ x,
                                          float2* __restrict__ xout,
                                          float2* __restrict__ h,
                                          float theta, bool init, int n) {
    int gwarp = (blockIdx.x * NTHR + threadIdx.x) >> 5;
    int nwarp = (gridDim.x * NTHR) >> 5;
    int lane  = threadIdx.x & 31;

    for (int row = gwarp; row < n; row += nwarp) {
        int beg = g_rowptr[row];
        int end = g_rowptr[row + 1];
        float a0 = 0.0f, a1 = 0.0f;
        int p = beg;
        for (; p + 3 < end; p += 4) {
            int2 e0 = g_edge[p],     e1 = g_edge[p + 1];
            int2 e2 = g_edge[p + 2], e3 = g_edge[p + 3];
            float2 v0 = x[e0.x * DH2 + lane];
            float2 v1 = x[e1.x * DH2 + lane];
            float2 v2 = x[e2.x * DH2 + lane];
            float2 v3 = x[e3.x * DH2 + lane];
            float w0 = __int_as_float(e0.y), w1 = __int_as_float(e1.y);
            float w2 = __int_as_float(e2.y), w3 = __int_as_float(e3.y);
            a0 = fmaf(w0, v0.x, a0); a1 = fmaf(w0, v0.y, a1);
            a0 = fmaf(w1, v1.x, a0); a1 = fmaf(w1, v1.y, a1);
            a0 = fmaf(w2, v2.x, a0); a1 = fmaf(w2, v2.y, a1);
            a0 = fmaf(w3, v3.x, a0); a1 = fmaf(w3, v3.y, a1);
        }
        for (; p < end; p++) {
            int2 e = g_edge[p];
            float2 v = x[e.x * DH2 + lane];
            float w = __int_as_float(e.y);
            a0 = fmaf(w, v.x, a0);
            a1 = fmaf(w, v.y, a1);
        }

        int o = row * DH2 + lane;
        if (xout) xout[o] = make_float2(a0, a1);
        if (init) {
            h[o] = make_float2(theta * a0, theta * a1);
        } else {
            float2 c = h[o];
            c.x += theta * a0;
            c.y += theta * a1;
            h[o] = c;
        }
    }
}

__global__ __launch_bounds__(NTHR, 1)
void k_all(const float* __restrict__ feat, const int* __restrict__ src,
           const int* __restrict__ dst, float* __restrict__ hout, int n, int E) {
    int tid = blockIdx.x * NTHR + threadIdx.x;
    int nth = gridDim.x * NTHR;
    __shared__ int s[SCAN_T];
    __shared__ int pref_s;

    // ---- Phase A: zero counters ----
    for (int i = tid; i < n; i += nth) { g_deg[i] = 0; g_cnt[i] = 0; }
    gbar();

    // ---- Phase B: degree histograms ----
    for (int e = tid; e < E; e += nth) {
        atomicAdd(&g_deg[src[e]], 1);
        atomicAdd(&g_cnt[dst[e]], 1);
    }
    gbar();

    // ---- Phase C: d^{-1/2} + per-tile scans of g_cnt ----
    for (int i = tid; i < n; i += nth) {
        int d = g_deg[i];
        g_dinv[i] = (d > 0) ? rsqrtf((float)d) : 0.0f;
    }
    int ntiles = (n + SCAN_T - 1) / SCAN_T;
    for (int tile = blockIdx.x; tile < ntiles; tile += gridDim.x) {
        int i = tile * SCAN_T + threadIdx.x;
        int v = (i < n) ? g_cnt[i] : 0;
        s[threadIdx.x] = v;
        __syncthreads();
        for (int off = 1; off < SCAN_T; off <<= 1) {
            int u = (threadIdx.x >= (unsigned)off) ? s[threadIdx.x - off] : 0;
            __syncthreads();
            s[threadIdx.x] += u;
            __syncthreads();
        }
        if (i < n) g_rowptr[i] = s[threadIdx.x] - v;     // exclusive within tile
        if (threadIdx.x == SCAN_T - 1) g_bsum[tile] = s[SCAN_T - 1];
        __syncthreads();
    }
    gbar();

    // ---- Phase D: add tile prefixes (redundant serial prefix per tile) ----
    for (int tile = blockIdx.x; tile < ntiles; tile += gridDim.x) {
        if (threadIdx.x == 0) {
            int run = 0;
            for (int j = 0; j < tile; j++) run += g_bsum[j];
            pref_s = run;
            if (tile == ntiles - 1) {
                int tot = run;
                for (int j = tile; j < ntiles; j++) tot += g_bsum[j];
                g_rowptr[n] = tot;
            }
        }
        __syncthreads();
        int i = tile * SCAN_T + threadIdx.x;
        if (i < n) {
            int r = g_rowptr[i] + pref_s;
            g_rowptr[i] = r;
            g_cursor[i] = r;
        }
        __syncthreads();
    }
    gbar();

    // ---- Phase E: fill CSC edge list (packed {col, w}) ----
    for (int e = tid; e < E; e += nth) {
        int d = dst[e];
        int sv = src[e];
        int pos = atomicAdd(&g_cursor[d], 1);
        g_edge[pos] = make_int2(sv, __float_as_int(g_dinv[sv] * g_dinv[d]));
    }
    gbar();

    // ---- Phases F-H: three SpMM hops ----
    float2* h2 = reinterpret_cast<float2*>(hout);
    const float2* f2 = reinterpret_cast<const float2*>(feat);
    spmm_pass(f2,   g_x1, h2, 0.80f, true,  n);   // h  = 0.8  * A f
    gbar();
    spmm_pass(g_x1, g_x2, h2, 0.15f, false, n);   // h += 0.15 * A x1
    gbar();
    spmm_pass(g_x2, (float2*)0, h2, 0.05f, false, n);  // h += 0.05 * A x2
}

extern "C" void kernel_launch(void* const* d_in, const int* in_sizes, int n_in,
                              void* d_out, int out_size) {
    const float* feat = (const float*)d_in[0];
    const int*   src  = (const int*)d_in[1];
    const int*   dst  = (const int*)d_in[2];
    float*       h    = (float*)d_out;

    int n = in_sizes[0] / DFEAT;   // 50000
    int E = in_sizes[1];           // 800000

    k_all<<<NBLK, NTHR>>>(feat, src, dst, h, n, E);
}

// round 9
// speedup vs baseline: 1.1662x; 1.1662x over previous
#include <cuda_runtime.h>

#define DFEAT 64
#define DF4 (DFEAT / 4)     // 16 float4 per row
#define MAX_NODES 50000
#define MAX_EDGES 800000
#define SCAN_B 1024
#define MAX_BLK ((MAX_NODES + SCAN_B - 1) / SCAN_B)

// ---- scratch (device globals; no allocation allowed) ----
__device__ int    g_deg[MAX_NODES];
__device__ int    g_cnt[MAX_NODES];
__device__ float  g_dinv[MAX_NODES];
__device__ int    g_rowptr[MAX_NODES + 1];
__device__ int    g_cursor[MAX_NODES];
__device__ int    g_bsum[MAX_BLK];
__device__ int2   g_edge[MAX_EDGES];            // {col, float_as_int(w)}
__device__ float4 g_x1[MAX_NODES * DF4];        // 16B-aligned by type
__device__ float4 g_x2[MAX_NODES * DF4];

__global__ void k_zero(int n) {
    int i = blockIdx.x * blockDim.x + threadIdx.x;
    if (i < n) { g_deg[i] = 0; g_cnt[i] = 0; }
}

__global__ void k_count(const int* __restrict__ src, const int* __restrict__ dst, int E) {
    int e = blockIdx.x * blockDim.x + threadIdx.x;
    if (e < E) {
        atomicAdd(&g_deg[src[e]], 1);
        atomicAdd(&g_cnt[dst[e]], 1);
    }
}

// Fused: blocks [0, nb) per-block scan of g_cnt; blocks [nb, 2nb) compute dinv.
__global__ void k_prep(int n, int nb) {
    if ((int)blockIdx.x < nb) {
        __shared__ int s[SCAN_B];
        int t = threadIdx.x;
        int i = blockIdx.x * SCAN_B + t;
        int v = (i < n) ? g_cnt[i] : 0;
        s[t] = v;
        __syncthreads();
        for (int off = 1; off < SCAN_B; off <<= 1) {
            int u = (t >= off) ? s[t - off] : 0;
            __syncthreads();
            s[t] += u;
            __syncthreads();
        }
        if (i < n) g_rowptr[i] = s[t] - v;
        if (t == SCAN_B - 1) g_bsum[blockIdx.x] = s[t];
    } else {
        int i = (blockIdx.x - nb) * SCAN_B + threadIdx.x;
        if (i < n) {
            int d = g_deg[i];
            g_dinv[i] = (d > 0) ? rsqrtf((float)d) : 0.0f;
        }
    }
}

// Scan phases 2+3: each block redundantly serial-scans the <=49 tile sums.
__global__ void k_scan3(int n, int nb) {
    __shared__ int pref;
    if (threadIdx.x == 0) {
        int run = 0;
        int b = (int)blockIdx.x;
        for (int j = 0; j < b; j++) run += g_bsum[j];
        pref = run;
        if (b == nb - 1) {
            int tot = run;
            for (int j = b; j < nb; j++) tot += g_bsum[j];
            g_rowptr[n] = tot;
        }
    }
    __syncthreads();
    int i = blockIdx.x * SCAN_B + threadIdx.x;
    if (i < n) {
        int r = g_rowptr[i] + pref;
        g_rowptr[i] = r;
        g_cursor[i] = r;
    }
}

__global__ void k_fill(const int* __restrict__ src, const int* __restrict__ dst, int E) {
    int e = blockIdx.x * blockDim.x + threadIdx.x;
    if (e < E) {
        int d = dst[e];
        int s = src[e];
        int pos = atomicAdd(&g_cursor[d], 1);
        g_edge[pos] = make_int2(s, __float_as_int(g_dinv[s] * g_dinv[d]));
    }
}

// One warp per output row; dual-edge float4 gathers.
// Lanes 0-15 process even edges of each pair, lanes 16-31 odd edges.
// Each lane accumulates 4 features (qi*4 .. qi*4+3); halves merged via shfl_xor(16).
// xin_sel: 0 = feat, 1 = g_x1, 2 = g_x2 ; xout_sel: 0 = none, 1 = g_x1, 2 = g_x2.
__global__ void k_spmm(const float* __restrict__ feat, float* __restrict__ h,
                       float theta, int init, int xin_sel, int xout_sel, int n) {
    int warp = (blockIdx.x * blockDim.x + threadIdx.x) >> 5;
    int lane = threadIdx.x & 31;
    if (warp >= n) return;
    int half = lane >> 4;       // which edge of the pair
    int qi   = lane & 15;       // float4 slot within the row

    const float4* __restrict__ x =
        (xin_sel == 0) ? reinterpret_cast<const float4*>(feat)
                       : ((xin_sel == 1) ? (const float4*)g_x1 : (const float4*)g_x2);
    float4* xout = (xout_sel == 0) ? (float4*)0 : ((xout_sel == 1) ? g_x1 : g_x2);

    int beg = g_rowptr[warp];
    int end = g_rowptr[warp + 1];

    float4 acc = make_float4(0.f, 0.f, 0.f, 0.f);

    int p = beg;
    // Main loop: 4 pairs = 8 edges per iteration; 8 independent gathers in flight.
    for (; p + 8 <= end; p += 8) {
        int2 e0 = g_edge[p + 0 + half];
        int2 e1 = g_edge[p + 2 + half];
        int2 e2 = g_edge[p + 4 + half];
        int2 e3 = g_edge[p + 6 + half];
        float4 v0 = x[e0.x * DF4 + qi];
        float4 v1 = x[e1.x * DF4 + qi];
        float4 v2 = x[e2.x * DF4 + qi];
        float4 v3 = x[e3.x * DF4 + qi];
        float w0 = __int_as_float(e0.y);
        float w1 = __int_as_float(e1.y);
        float w2 = __int_as_float(e2.y);
        float w3 = __int_as_float(e3.y);
        acc.x = fmaf(w0, v0.x, acc.x); acc.y = fmaf(w0, v0.y, acc.y);
        acc.z = fmaf(w0, v0.z, acc.z); acc.w = fmaf(w0, v0.w, acc.w);
        acc.x = fmaf(w1, v1.x, acc.x); acc.y = fmaf(w1, v1.y, acc.y);
        acc.z = fmaf(w1, v1.z, acc.z); acc.w = fmaf(w1, v1.w, acc.w);
        acc.x = fmaf(w2, v2.x, acc.x); acc.y = fmaf(w2, v2.y, acc.y);
        acc.z = fmaf(w2, v2.z, acc.z); acc.w = fmaf(w2, v2.w, acc.w);
        acc.x = fmaf(w3, v3.x, acc.x); acc.y = fmaf(w3, v3.y, acc.y);
        acc.z = fmaf(w3, v3.z, acc.z); acc.w = fmaf(w3, v3.w, acc.w);
    }
    // Pair tail
    for (; p + 2 <= end; p += 2) {
        int2 e = g_edge[p + half];
        float w = __int_as_float(e.y);
        float4 v = x[e.x * DF4 + qi];
        acc.x = fmaf(w, v.x, acc.x); acc.y = fmaf(w, v.y, acc.y);
        acc.z = fmaf(w, v.z, acc.z); acc.w = fmaf(w, v.w, acc.w);
    }
    // Single-edge tail: upper half contributes zero weight.
    if (p < end) {
        int2 e = g_edge[p];
        float w = half ? 0.0f : __int_as_float(e.y);
        float4 v = x[e.x * DF4 + qi];
        acc.x = fmaf(w, v.x, acc.x); acc.y = fmaf(w, v.y, acc.y);
        acc.z = fmaf(w, v.z, acc.z); acc.w = fmaf(w, v.w, acc.w);
    }

    // Merge the two half-warp partial sums (both halves end with the total).
    acc.x += __shfl_xor_sync(0xffffffffu, acc.x, 16);
    acc.y += __shfl_xor_sync(0xffffffffu, acc.y, 16);
    acc.z += __shfl_xor_sync(0xffffffffu, acc.z, 16);
    acc.w += __shfl_xor_sync(0xffffffffu, acc.w, 16);

    int o = warp * DF4 + qi;
    // Split output duties: half 0 writes x_next (if any), half 1 updates h.
    if (xout && half == 0) {
        xout[o] = acc;
    }
    bool do_h = xout ? (half == 1) : (half == 0);
    if (do_h) {
        float4* h4 = reinterpret_cast<float4*>(h);
        if (init) {
            h4[o] = make_float4(theta * acc.x, theta * acc.y,
                                theta * acc.z, theta * acc.w);
        } else {
            float4 c = h4[o];
            c.x = fmaf(theta, acc.x, c.x);
            c.y = fmaf(theta, acc.y, c.y);
            c.z = fmaf(theta, acc.z, c.z);
            c.w = fmaf(theta, acc.w, c.w);
            h4[o] = c;
        }
    }
}

extern "C" void kernel_launch(void* const* d_in, const int* in_sizes, int n_in,
                              void* d_out, int out_size) {
    const float* feat = (const float*)d_in[0];
    const int*   src  = (const int*)d_in[1];
    const int*   dst  = (const int*)d_in[2];
    float*       h    = (float*)d_out;

    int n = in_sizes[0] / DFEAT;   // 50000
    int E = in_sizes[1];           // 800000

    int tb = 256;
    int gn = (n + tb - 1) / tb;
    int ge = (E + tb - 1) / tb;
    int nb = (n + SCAN_B - 1) / SCAN_B;

    k_zero<<<gn, tb>>>(n);
    k_count<<<ge, tb>>>(src, dst, E);
    k_prep<<<2 * nb, SCAN_B>>>(n, nb);
    k_scan3<<<nb, SCAN_B>>>(n, nb);
    k_fill<<<ge, tb>>>(src, dst, E);

    int gs = (n + 7) / 8;   // one warp per row, 8 warps/block
    // h  = 0.80 * (A @ f)      ; x1 -> g_x1
    k_spmm<<<gs, tb>>>(feat, h, 0.80f, 1, 0, 1, n);
    // h += 0.15 * (A @ x1)     ; x2 -> g_x2
    k_spmm<<<gs, tb>>>(feat, h, 0.15f, 0, 1, 2, n);
    // h += 0.05 * (A @ x2)
    k_spmm<<<gs, tb>>>(feat, h, 0.05f, 0, 2, 0, n);
}

// round 11
// speedup vs baseline: 1.2469x; 1.0692x over previous
#include <cuda_runtime.h>

#define DFEAT 64
#define DF4 (DFEAT / 4)     // 16 float4 per row
#define MAX_NODES 50000
#define MAX_EDGES 800000
#define SCAN_B 1024
#define MAX_BLK ((MAX_NODES + SCAN_B - 1) / SCAN_B)

// ---- scratch (device globals; no allocation allowed) ----
__device__ int    g_deg[MAX_NODES];
__device__ int    g_cnt[MAX_NODES];
__device__ float  g_dinv[MAX_NODES];
__device__ int    g_rowptr[MAX_NODES + 1];
__device__ int    g_cursor[MAX_NODES];
__device__ int    g_bsum[MAX_BLK];
__device__ int2   g_edge[MAX_EDGES];            // {col, float_as_int(w)}
__device__ float4 g_x1[MAX_NODES * DF4];
__device__ float4 g_x2[MAX_NODES * DF4];

__global__ void k_zero(int n) {
    int i = blockIdx.x * blockDim.x + threadIdx.x;
    if (i < n) { g_deg[i] = 0; g_cnt[i] = 0; }
}

__global__ void k_count(const int* __restrict__ src, const int* __restrict__ dst, int E) {
    int e = blockIdx.x * blockDim.x + threadIdx.x;
    if (e < E) {
        atomicAdd(&g_deg[src[e]], 1);
        atomicAdd(&g_cnt[dst[e]], 1);
    }
}

// Fused: blocks [0, nb) per-block scan of g_cnt; blocks [nb, 2nb) compute dinv.
__global__ void k_prep(int n, int nb) {
    if ((int)blockIdx.x < nb) {
        __shared__ int s[SCAN_B];
        int t = threadIdx.x;
        int i = blockIdx.x * SCAN_B + t;
        int v = (i < n) ? g_cnt[i] : 0;
        s[t] = v;
        __syncthreads();
        for (int off = 1; off < SCAN_B; off <<= 1) {
            int u = (t >= off) ? s[t - off] : 0;
            __syncthreads();
            s[t] += u;
            __syncthreads();
        }
        if (i < n) g_rowptr[i] = s[t] - v;
        if (t == SCAN_B - 1) g_bsum[blockIdx.x] = s[t];
    } else {
        int i = (blockIdx.x - nb) * SCAN_B + threadIdx.x;
        if (i < n) {
            int d = g_deg[i];
            g_dinv[i] = (d > 0) ? rsqrtf((float)d) : 0.0f;
        }
    }
}

// Scan phases 2+3: tile sums loaded IN PARALLEL (one per thread), then a
// shared-mem scan — no serial dependent-load chain (was 5.8us, ~240cyc x 48).
__global__ void k_scan3(int n, int nb) {
    __shared__ int s[64];    // nb <= 49
    int t = threadIdx.x;
    if (t < 64) s[t] = (t < nb) ? g_bsum[t] : 0;
    __syncthreads();
    if (t < 64) {
        // Hillis-Steele inclusive scan over 64 entries by first 64 threads.
        for (int off = 1; off < 64; off <<= 1) {
            int u = (t >= off) ? s[t - off] : 0;
            __syncthreads();
            s[t] += u;
            __syncthreads();
        }
    } else {
        for (int off = 1; off < 64; off <<= 1) { __syncthreads(); __syncthreads(); }
    }
    int b = (int)blockIdx.x;
    int pref = (b > 0) ? s[b - 1] : 0;      // exclusive prefix of this tile
    if (b == nb - 1 && t == 0) g_rowptr[n] = s[nb - 1];
    int i = b * SCAN_B + t;
    if (i < n) {
        int r = g_rowptr[i] + pref;
        g_rowptr[i] = r;
        g_cursor[i] = r;
    }
}

__global__ void k_fill(const int* __restrict__ src, const int* __restrict__ dst, int E) {
    int e = blockIdx.x * blockDim.x + threadIdx.x;
    if (e < E) {
        int d = dst[e];
        int s = src[e];
        int pos = atomicAdd(&g_cursor[d], 1);
        g_edge[pos] = make_int2(s, __float_as_int(g_dinv[s] * g_dinv[d]));
    }
}

// One row per HALF-WARP: 16 lanes x float4 = full 64-feature row.
// Doubles rows-in-flight per SM vs one-row-per-warp at equal occupancy;
// the two half-warps in a warp have fully independent dependency chains.
// xin_sel: 0 = feat, 1 = g_x1, 2 = g_x2 ; xout_sel: 0 = none, 1 = g_x1, 2 = g_x2.
__global__ void k_spmm(const float* __restrict__ feat, float* __restrict__ h,
                       float theta, int init, int xin_sel, int xout_sel, int n) {
    int row = (blockIdx.x * blockDim.x + threadIdx.x) >> 4;
    int qi  = threadIdx.x & 15;          // float4 slot within the row
    if (row >= n) return;

    const float4* __restrict__ x =
        (xin_sel == 0) ? reinterpret_cast<const float4*>(feat)
                       : ((xin_sel == 1) ? (const float4*)g_x1 : (const float4*)g_x2);
    float4* xout = (xout_sel == 0) ? (float4*)0 : ((xout_sel == 1) ? g_x1 : g_x2);

    int beg = g_rowptr[row];
    int end = g_rowptr[row + 1];

    float4 acc = make_float4(0.f, 0.f, 0.f, 0.f);

    int p = beg;
    for (; p + 4 <= end; p += 4) {
        int2 e0 = g_edge[p],     e1 = g_edge[p + 1];
        int2 e2 = g_edge[p + 2], e3 = g_edge[p + 3];
        float4 v0 = x[e0.x * DF4 + qi];
        float4 v1 = x[e1.x * DF4 + qi];
        float4 v2 = x[e2.x * DF4 + qi];
        float4 v3 = x[e3.x * DF4 + qi];
        float w0 = __int_as_float(e0.y), w1 = __int_as_float(e1.y);
        float w2 = __int_as_float(e2.y), w3 = __int_as_float(e3.y);
        acc.x = fmaf(w0, v0.x, acc.x); acc.y = fmaf(w0, v0.y, acc.y);
        acc.z = fmaf(w0, v0.z, acc.z); acc.w = fmaf(w0, v0.w, acc.w);
        acc.x = fmaf(w1, v1.x, acc.x); acc.y = fmaf(w1, v1.y, acc.y);
        acc.z = fmaf(w1, v1.z, acc.z); acc.w = fmaf(w1, v1.w, acc.w);
        acc.x = fmaf(w2, v2.x, acc.x); acc.y = fmaf(w2, v2.y, acc.y);
        acc.z = fmaf(w2, v2.z, acc.z); acc.w = fmaf(w2, v2.w, acc.w);
        acc.x = fmaf(w3, v3.x, acc.x); acc.y = fmaf(w3, v3.y, acc.y);
        acc.z = fmaf(w3, v3.z, acc.z); acc.w = fmaf(w3, v3.w, acc.w);
    }
    for (; p < end; p++) {
        int2 e = g_edge[p];
        float w = __int_as_float(e.y);
        float4 v = x[e.x * DF4 + qi];
        acc.x = fmaf(w, v.x, acc.x); acc.y = fmaf(w, v.y, acc.y);
        acc.z = fmaf(w, v.z, acc.z); acc.w = fmaf(w, v.w, acc.w);
    }

    int o = row * DF4 + qi;
    if (xout) xout[o] = acc;
    float4* h4 = reinterpret_cast<float4*>(h);
    if (init) {
        h4[o] = make_float4(theta * acc.x, theta * acc.y,
                            theta * acc.z, theta * acc.w);
    } else {
        float4 c = h4[o];
        c.x = fmaf(theta, acc.x, c.x);
        c.y = fmaf(theta, acc.y, c.y);
        c.z = fmaf(theta, acc.z, c.z);
        c.w = fmaf(theta, acc.w, c.w);
        h4[o] = c;
    }
}

extern "C" void kernel_launch(void* const* d_in, const int* in_sizes, int n_in,
                              void* d_out, int out_size) {
    const float* feat = (const float*)d_in[0];
    const int*   src  = (const int*)d_in[1];
    const int*   dst  = (const int*)d_in[2];
    float*       h    = (float*)d_out;

    int n = in_sizes[0] / DFEAT;   // 50000
    int E = in_sizes[1];           // 800000

    int tb = 256;
    int gn = (n + tb - 1) / tb;
    int ge = (E + tb - 1) / tb;
    int nb = (n + SCAN_B - 1) / SCAN_B;

    k_zero<<<gn, tb>>>(n);
    k_count<<<ge, tb>>>(src, dst, E);
    k_prep<<<2 * nb, SCAN_B>>>(n, nb);
    k_scan3<<<nb, SCAN_B>>>(n, nb);
    k_fill<<<ge, tb>>>(src, dst, E);

    int gs = (n + 15) / 16;   // one row per half-warp, 16 half-warps/block
    // h  = 0.80 * (A @ f)      ; x1 -> g_x1
    k_spmm<<<gs, tb>>>(feat, h, 0.80f, 1, 0, 1, n);
    // h += 0.15 * (A @ x1)     ; x2 -> g_x2
    k_spmm<<<gs, tb>>>(feat, h, 0.15f, 0, 1, 2, n);
    // h += 0.05 * (A @ x2)
    k_spmm<<<gs, tb>>>(feat, h, 0.05f, 0, 2, 0, n);
}